// round 1
// baseline (speedup 1.0000x reference)
#include <cuda_runtime.h>
#include <cuda_bf16.h>
#include <cstdint>

// Problem constants
#define BATCH 32
#define DIM   512
#define HW    1024          // 32*32
#define NTOK  (BATCH*HW)    // 32768
#define NCODE 4096
#define TOTAL_OUT ((long long)BATCH * DIM * HW)   // 16777216

// ---------------- device globals (scratch; no allocations allowed) -------------
__device__ float  g_enorm[NCODE];
__device__ int    g_kidx[NTOK];
__device__ double g_loss_acc;

// ---------------- f32x2 helpers ------------------------------------------------
__device__ __forceinline__ unsigned long long pack2(float a, float b) {
    unsigned long long r;
    asm("mov.b64 %0, {%1, %2};" : "=l"(r) : "f"(a), "f"(b));
    return r;
}
__device__ __forceinline__ void ffma2(unsigned long long& d,
                                      unsigned long long a,
                                      unsigned long long b) {
    asm("fma.rn.f32x2 %0, %1, %2, %0;" : "+l"(d) : "l"(a), "l"(b));
}
__device__ __forceinline__ float2 unpack2(unsigned long long v) {
    float lo, hi;
    asm("mov.b64 {%0, %1}, %2;" : "=f"(lo), "=f"(hi) : "l"(v));
    return make_float2(lo, hi);
}

// ---------------- kernel 1: codebook norms + loss reset ------------------------
__global__ void enorm_kernel(const float* __restrict__ E) {
    __shared__ float red[128];
    int k = blockIdx.x;
    const float* row = E + (size_t)k * DIM;
    float s = 0.f;
    for (int d = threadIdx.x; d < DIM; d += 128) {
        float v = row[d];
        s = fmaf(v, v, s);
    }
    red[threadIdx.x] = s;
    __syncthreads();
    for (int o = 64; o > 0; o >>= 1) {
        if (threadIdx.x < o) red[threadIdx.x] += red[threadIdx.x + o];
        __syncthreads();
    }
    if (threadIdx.x == 0) g_enorm[k] = red[0];
    if (blockIdx.x == 0 && threadIdx.x == 0) g_loss_acc = 0.0;
}

// ---------------- kernel 2: fused distance GEMM + argmin -----------------------
// Grid: 256 blocks (one per 128-token tile), 256 threads.
// Thread (ty=tid>>4, tx=tid&15) computes an 8x8 micro-tile:
//   rows  = ty*8 .. ty*8+7   (tokens within tile)
//   cols  = tx*8 .. tx*8+7   (codes within 128-code tile)
// score(n,k) = ||e_k||^2 - 2 * dot(z_n, e_k)   (||z||^2 is constant per row)
__global__ __launch_bounds__(256, 2)
void argmin_kernel(const float* __restrict__ in, const float* __restrict__ E) {
    __shared__ float Zs[16][132];   // [d-chunk][token]
    __shared__ float Es[16][132];   // [d-chunk][code]
    __shared__ float en_s[128];

    const int tid = threadIdx.x;
    const int ty = tid >> 4;        // 0..15 row group
    const int tx = tid & 15;        // 0..15 col group
    const int b   = blockIdx.x >> 3;          // 0..31
    const int hw0 = (blockIdx.x & 7) << 7;    // 0,128,...,896
    const float* inb = in + ((size_t)b * DIM) * HW + hw0;

    float best_val[8];
    int   best_idx[8];
#pragma unroll
    for (int i = 0; i < 8; i++) { best_val[i] = 3.4e38f; best_idx[i] = 0; }

    for (int k0 = 0; k0 < NCODE; k0 += 128) {
        __syncthreads();  // previous epilogue done reading en_s
        if (tid < 128) en_s[tid] = g_enorm[k0 + tid];

        unsigned long long acc[8][4];
#pragma unroll
        for (int i = 0; i < 8; i++)
#pragma unroll
            for (int j = 0; j < 4; j++) acc[i][j] = 0ULL;

        for (int d0 = 0; d0 < DIM; d0 += 16) {
            __syncthreads();  // previous compute done reading smem
            // Load Z tile: Zs[dd][tok] = in[b][d0+dd][hw0+tok]  (coalesced over tok)
#pragma unroll
            for (int i = tid; i < 2048; i += 256) {
                int dd = i >> 7;
                int t  = i & 127;
                Zs[dd][t] = inb[(size_t)(d0 + dd) * HW + t];
            }
            // Load E tile: Es[dd][c] = E[k0+c][d0+dd]  (16-float segments)
#pragma unroll
            for (int i = tid; i < 2048; i += 256) {
                int dd = i & 15;
                int c  = i >> 4;
                Es[dd][c] = E[(size_t)(k0 + c) * DIM + d0 + dd];
            }
            __syncthreads();

#pragma unroll
            for (int dd = 0; dd < 16; dd++) {
                float4 za = *(const float4*)&Zs[dd][ty * 8];
                float4 zb = *(const float4*)&Zs[dd][ty * 8 + 4];
                ulonglong2 ea = *(const ulonglong2*)&Es[dd][tx * 8];
                ulonglong2 eb = *(const ulonglong2*)&Es[dd][tx * 8 + 4];
                unsigned long long z2[8];
                z2[0] = pack2(za.x, za.x); z2[1] = pack2(za.y, za.y);
                z2[2] = pack2(za.z, za.z); z2[3] = pack2(za.w, za.w);
                z2[4] = pack2(zb.x, zb.x); z2[5] = pack2(zb.y, zb.y);
                z2[6] = pack2(zb.z, zb.z); z2[7] = pack2(zb.w, zb.w);
#pragma unroll
                for (int i = 0; i < 8; i++) {
                    ffma2(acc[i][0], z2[i], ea.x);
                    ffma2(acc[i][1], z2[i], ea.y);
                    ffma2(acc[i][2], z2[i], eb.x);
                    ffma2(acc[i][3], z2[i], eb.y);
                }
            }
        }

        // Epilogue: score = ||e||^2 - 2*dot ; running min (ascending idx keeps
        // first-match tie-break like jnp.argmin)
#pragma unroll
        for (int i = 0; i < 8; i++) {
#pragma unroll
            for (int jp = 0; jp < 4; jp++) {
                float2 f = unpack2(acc[i][jp]);
                int c0 = tx * 8 + jp * 2;
                float s0 = fmaf(-2.f, f.x, en_s[c0]);
                float s1 = fmaf(-2.f, f.y, en_s[c0 + 1]);
                if (s0 < best_val[i]) { best_val[i] = s0; best_idx[i] = k0 + c0; }
                if (s1 < best_val[i]) { best_val[i] = s1; best_idx[i] = k0 + c0 + 1; }
            }
        }
    }

    // Reduce across the 16 threads (one half-warp, same ty) that share rows.
#pragma unroll
    for (int i = 0; i < 8; i++) {
        float v = best_val[i];
        int   idx = best_idx[i];
#pragma unroll
        for (int off = 8; off > 0; off >>= 1) {
            float ov = __shfl_down_sync(0xffffffffu, v, off, 16);
            int   oi = __shfl_down_sync(0xffffffffu, idx, off, 16);
            if (ov < v || (ov == v && oi < idx)) { v = ov; idx = oi; }
        }
        if (tx == 0) g_kidx[b * HW + hw0 + ty * 8 + i] = idx;
    }
}

// ---------------- kernel 3: gather -> NCHW output + loss partial ---------------
// Grid: B*D = 16384 blocks, 256 threads. Coalesced in/out over hw; E reads are
// scattered but L2-resident (8MB codebook).
__global__ void gather_kernel(const float* __restrict__ in,
                              const float* __restrict__ E,
                              float* __restrict__ out) {
    int bd = blockIdx.x;
    int b = bd >> 9;
    int d = bd & 511;
    const int* kp = g_kidx + b * HW;
    size_t base = ((size_t)b * DIM + d) * HW;
    float local = 0.f;
#pragma unroll
    for (int it = 0; it < 4; it++) {
        int hw = it * 256 + threadIdx.x;
        int k = kp[hw];
        float e = E[(size_t)k * DIM + d];
        float z = in[base + hw];
        out[base + hw] = e;
        float df = z - e;
        local = fmaf(df, df, local);
    }
    __shared__ float red[256];
    red[threadIdx.x] = local;
    __syncthreads();
    for (int o = 128; o > 0; o >>= 1) {
        if (threadIdx.x < o) red[threadIdx.x] += red[threadIdx.x + o];
        __syncthreads();
    }
    if (threadIdx.x == 0) atomicAdd(&g_loss_acc, (double)red[0]);
}

// ---------------- kernel 4: final loss scalar ----------------------------------
__global__ void loss_kernel(float* __restrict__ out, int out_size) {
    if ((long long)out_size > TOTAL_OUT) {
        // loss = e_loss + 0.25*e_loss = 1.25 * mean((z - q)^2)
        double mean = g_loss_acc / (double)TOTAL_OUT;
        out[TOTAL_OUT] = (float)(1.25 * mean);
    }
}

// ---------------- launch --------------------------------------------------------
extern "C" void kernel_launch(void* const* d_in, const int* in_sizes, int n_in,
                              void* d_out, int out_size) {
    const float* in = (const float*)d_in[0];   // [32,512,32,32] fp32
    const float* E  = (const float*)d_in[1];   // [4096,512] fp32
    float* out = (float*)d_out;

    enorm_kernel<<<NCODE, 128>>>(E);
    argmin_kernel<<<NTOK / 128, 256>>>(in, E);
    gather_kernel<<<BATCH * DIM, 256>>>(in, E, out);
    loss_kernel<<<1, 1>>>(out, out_size);
}

// round 3
// speedup vs baseline: 1.6603x; 1.6603x over previous
#include <cuda_runtime.h>
#include <cuda_bf16.h>
#include <cstdint>

// Problem constants
#define BATCH 32
#define DIM   512
#define HW    1024          // 32*32
#define NTOK  (BATCH*HW)    // 32768
#define NCODE 4096
#define TOTAL_OUT ((long long)BATCH * DIM * HW)   // 16777216

// ---------------- device globals (scratch; no allocations allowed) -------------
__device__ float  g_enorm[NCODE];
__device__ int    g_kidx[NTOK];
__device__ double g_loss_acc;

// ---------------- f32x2 helpers ------------------------------------------------
__device__ __forceinline__ unsigned long long pack2(float a, float b) {
    unsigned long long r;
    asm("mov.b64 %0, {%1, %2};" : "=l"(r) : "f"(a), "f"(b));
    return r;
}
__device__ __forceinline__ void ffma2(unsigned long long& d,
                                      unsigned long long a,
                                      unsigned long long b) {
    asm("fma.rn.f32x2 %0, %1, %2, %0;" : "+l"(d) : "l"(a), "l"(b));
}
__device__ __forceinline__ float2 unpack2(unsigned long long v) {
    float lo, hi;
    asm("mov.b64 {%0, %1}, %2;" : "=f"(lo), "=f"(hi) : "l"(v));
    return make_float2(lo, hi);
}

// ---------------- kernel 1: codebook norms + loss reset ------------------------
__global__ void enorm_kernel(const float* __restrict__ E) {
    __shared__ float red[128];
    int k = blockIdx.x;
    const float* row = E + (size_t)k * DIM;
    float s = 0.f;
    for (int d = threadIdx.x; d < DIM; d += 128) {
        float v = row[d];
        s = fmaf(v, v, s);
    }
    red[threadIdx.x] = s;
    __syncthreads();
    for (int o = 64; o > 0; o >>= 1) {
        if (threadIdx.x < o) red[threadIdx.x] += red[threadIdx.x + o];
        __syncthreads();
    }
    if (threadIdx.x == 0) g_enorm[k] = red[0];
    if (blockIdx.x == 0 && threadIdx.x == 0) g_loss_acc = 0.0;
}

// ---------------- kernel 2: fused distance GEMM + argmin -----------------------
// Grid: 256 blocks (one per 128-token tile), 256 threads.
// Thread (ty=tid>>4, tx=tid&15) computes an 8x8 micro-tile:
//   rows  = ty*8 .. ty*8+7   (tokens within tile)
//   cols  = tx*8 .. tx*8+7   (codes within 128-code tile)
// score(n,k) = ||e_k||^2 - 2 * dot(z_n, e_k)   (||z||^2 is constant per row)
__global__ __launch_bounds__(256, 2)
void argmin_kernel(const float* __restrict__ in, const float* __restrict__ E) {
    __shared__ float Zs[16][132];   // [d-chunk][token]
    __shared__ float Es[16][132];   // [d-chunk][code]
    __shared__ float en_s[128];

    const int tid = threadIdx.x;
    const int ty = tid >> 4;        // 0..15 row group
    const int tx = tid & 15;        // 0..15 col group
    const int b   = blockIdx.x >> 3;          // 0..31
    const int hw0 = (blockIdx.x & 7) << 7;    // 0,128,...,896
    const float* inb = in + ((size_t)b * DIM) * HW + hw0;

    float best_val[8];
    int   best_idx[8];
#pragma unroll
    for (int i = 0; i < 8; i++) { best_val[i] = 3.4e38f; best_idx[i] = 0; }

    for (int k0 = 0; k0 < NCODE; k0 += 128) {
        __syncthreads();  // previous epilogue done reading en_s
        if (tid < 128) en_s[tid] = g_enorm[k0 + tid];

        unsigned long long acc[8][4];
#pragma unroll
        for (int i = 0; i < 8; i++)
#pragma unroll
            for (int j = 0; j < 4; j++) acc[i][j] = 0ULL;

        for (int d0 = 0; d0 < DIM; d0 += 16) {
            __syncthreads();  // previous compute done reading smem
            // Load Z tile: Zs[dd][tok] = in[b][d0+dd][hw0+tok]  (coalesced over tok)
#pragma unroll
            for (int i = tid; i < 2048; i += 256) {
                int dd = i >> 7;
                int t  = i & 127;
                Zs[dd][t] = inb[(size_t)(d0 + dd) * HW + t];
            }
            // Load E tile: Es[dd][c] = E[k0+c][d0+dd]  (16-float segments)
#pragma unroll
            for (int i = tid; i < 2048; i += 256) {
                int dd = i & 15;
                int c  = i >> 4;
                Es[dd][c] = E[(size_t)(k0 + c) * DIM + d0 + dd];
            }
            __syncthreads();

#pragma unroll
            for (int dd = 0; dd < 16; dd++) {
                float4 za = *(const float4*)&Zs[dd][ty * 8];
                float4 zb = *(const float4*)&Zs[dd][ty * 8 + 4];
                ulonglong2 ea = *(const ulonglong2*)&Es[dd][tx * 8];
                ulonglong2 eb = *(const ulonglong2*)&Es[dd][tx * 8 + 4];
                unsigned long long z2[8];
                z2[0] = pack2(za.x, za.x); z2[1] = pack2(za.y, za.y);
                z2[2] = pack2(za.z, za.z); z2[3] = pack2(za.w, za.w);
                z2[4] = pack2(zb.x, zb.x); z2[5] = pack2(zb.y, zb.y);
                z2[6] = pack2(zb.z, zb.z); z2[7] = pack2(zb.w, zb.w);
#pragma unroll
                for (int i = 0; i < 8; i++) {
                    ffma2(acc[i][0], z2[i], ea.x);
                    ffma2(acc[i][1], z2[i], ea.y);
                    ffma2(acc[i][2], z2[i], eb.x);
                    ffma2(acc[i][3], z2[i], eb.y);
                }
            }
        }

        // Epilogue: score = ||e||^2 - 2*dot ; running min (ascending idx keeps
        // first-match tie-break like jnp.argmin)
#pragma unroll
        for (int i = 0; i < 8; i++) {
#pragma unroll
            for (int jp = 0; jp < 4; jp++) {
                float2 f = unpack2(acc[i][jp]);
                int c0 = tx * 8 + jp * 2;
                float s0 = fmaf(-2.f, f.x, en_s[c0]);
                float s1 = fmaf(-2.f, f.y, en_s[c0 + 1]);
                if (s0 < best_val[i]) { best_val[i] = s0; best_idx[i] = k0 + c0; }
                if (s1 < best_val[i]) { best_val[i] = s1; best_idx[i] = k0 + c0 + 1; }
            }
        }
    }

    // Reduce across the 16 threads (one half-warp, same ty) that share rows.
#pragma unroll
    for (int i = 0; i < 8; i++) {
        float v = best_val[i];
        int   idx = best_idx[i];
#pragma unroll
        for (int off = 8; off > 0; off >>= 1) {
            float ov = __shfl_down_sync(0xffffffffu, v, off, 16);
            int   oi = __shfl_down_sync(0xffffffffu, idx, off, 16);
            if (ov < v || (ov == v && oi < idx)) { v = ov; idx = oi; }
        }
        if (tx == 0) g_kidx[b * HW + hw0 + ty * 8 + i] = idx;
    }
}

// ---------------- kernel 3: gather -> NCHW output + loss partial ---------------
// Grid: B*D = 16384 blocks, 256 threads. Coalesced in/out over hw; E reads are
// scattered but L2-resident (8MB codebook).
__global__ void gather_kernel(const float* __restrict__ in,
                              const float* __restrict__ E,
                              float* __restrict__ out) {
    int bd = blockIdx.x;
    int b = bd >> 9;
    int d = bd & 511;
    const int* kp = g_kidx + b * HW;
    size_t base = ((size_t)b * DIM + d) * HW;
    float local = 0.f;
#pragma unroll
    for (int it = 0; it < 4; it++) {
        int hw = it * 256 + threadIdx.x;
        int k = kp[hw];
        float e = E[(size_t)k * DIM + d];
        float z = in[base + hw];
        out[base + hw] = e;
        float df = z - e;
        local = fmaf(df, df, local);
    }
    __shared__ float red[256];
    red[threadIdx.x] = local;
    __syncthreads();
    for (int o = 128; o > 0; o >>= 1) {
        if (threadIdx.x < o) red[threadIdx.x] += red[threadIdx.x + o];
        __syncthreads();
    }
    if (threadIdx.x == 0) atomicAdd(&g_loss_acc, (double)red[0]);
}

// ---------------- kernel 4: final loss scalar ----------------------------------
__global__ void loss_kernel(float* __restrict__ out, int out_size) {
    if ((long long)out_size > TOTAL_OUT) {
        // loss = e_loss + 0.25*e_loss = 1.25 * mean((z - q)^2)
        double mean = g_loss_acc / (double)TOTAL_OUT;
        out[TOTAL_OUT] = (float)(1.25 * mean);
    }
}

// ---------------- launch --------------------------------------------------------
extern "C" void kernel_launch(void* const* d_in, const int* in_sizes, int n_in,
                              void* d_out, int out_size) {
    const float* in = (const float*)d_in[0];   // [32,512,32,32] fp32
    const float* E  = (const float*)d_in[1];   // [4096,512] fp32
    float* out = (float*)d_out;

    enorm_kernel<<<NCODE, 128>>>(E);
    argmin_kernel<<<NTOK / 128, 256>>>(in, E);
    gather_kernel<<<BATCH * DIM, 256>>>(in, E, out);
    loss_kernel<<<1, 1>>>(out, out_size);
}

// round 4
// speedup vs baseline: 1.6623x; 1.0012x over previous
#include <cuda_runtime.h>
#include <cuda_bf16.h>
#include <cstdint>

// Problem constants
#define BATCH 32
#define DIM   512
#define HW    1024          // 32*32
#define NTOK  (BATCH*HW)    // 32768
#define NCODE 4096
#define TOTAL_OUT ((long long)BATCH * DIM * HW)   // 16777216

// ---------------- device globals (scratch; no allocations allowed) -------------
__device__ float  g_enorm[NCODE];
__device__ int    g_kidx[NTOK];
__device__ double g_loss_acc;

// ---------------- f32x2 helpers ------------------------------------------------
__device__ __forceinline__ unsigned long long pack2(float a, float b) {
    unsigned long long r;
    asm("mov.b64 %0, {%1, %2};" : "=l"(r) : "f"(a), "f"(b));
    return r;
}
__device__ __forceinline__ void ffma2(unsigned long long& d,
                                      unsigned long long a,
                                      unsigned long long b) {
    asm("fma.rn.f32x2 %0, %1, %2, %0;" : "+l"(d) : "l"(a), "l"(b));
}
__device__ __forceinline__ float2 unpack2(unsigned long long v) {
    float lo, hi;
    asm("mov.b64 {%0, %1}, %2;" : "=f"(lo), "=f"(hi) : "l"(v));
    return make_float2(lo, hi);
}

// ---------------- kernel 1: codebook norms + loss reset ------------------------
__global__ void enorm_kernel(const float* __restrict__ E) {
    __shared__ float red[128];
    int k = blockIdx.x;
    const float* row = E + (size_t)k * DIM;
    float s = 0.f;
    for (int d = threadIdx.x; d < DIM; d += 128) {
        float v = row[d];
        s = fmaf(v, v, s);
    }
    red[threadIdx.x] = s;
    __syncthreads();
    for (int o = 64; o > 0; o >>= 1) {
        if (threadIdx.x < o) red[threadIdx.x] += red[threadIdx.x + o];
        __syncthreads();
    }
    if (threadIdx.x == 0) g_enorm[k] = red[0];
    if (blockIdx.x == 0 && threadIdx.x == 0) g_loss_acc = 0.0;
}

// ---------------- kernel 2: fused distance GEMM + argmin -----------------------
// Grid: 256 blocks (one per 128-token tile), 256 threads.
// Thread (ty=tid>>4, tx=tid&15) computes an 8x8 micro-tile:
//   rows  = ty*8 .. ty*8+7   (tokens within tile)
//   cols  = tx*8 .. tx*8+7   (codes within 128-code tile)
// score(n,k) = ||e_k||^2 - 2 * dot(z_n, e_k)   (||z||^2 is constant per row)
__global__ __launch_bounds__(256, 2)
void argmin_kernel(const float* __restrict__ in, const float* __restrict__ E) {
    __shared__ float Zs[16][132];   // [d-chunk][token]
    __shared__ float Es[16][132];   // [d-chunk][code]
    __shared__ float en_s[128];

    const int tid = threadIdx.x;
    const int ty = tid >> 4;        // 0..15 row group
    const int tx = tid & 15;        // 0..15 col group
    const int b   = blockIdx.x >> 3;          // 0..31
    const int hw0 = (blockIdx.x & 7) << 7;    // 0,128,...,896
    const float* inb = in + ((size_t)b * DIM) * HW + hw0;

    float best_val[8];
    int   best_idx[8];
#pragma unroll
    for (int i = 0; i < 8; i++) { best_val[i] = 3.4e38f; best_idx[i] = 0; }

    for (int k0 = 0; k0 < NCODE; k0 += 128) {
        __syncthreads();  // previous epilogue done reading en_s
        if (tid < 128) en_s[tid] = g_enorm[k0 + tid];

        unsigned long long acc[8][4];
#pragma unroll
        for (int i = 0; i < 8; i++)
#pragma unroll
            for (int j = 0; j < 4; j++) acc[i][j] = 0ULL;

        for (int d0 = 0; d0 < DIM; d0 += 16) {
            __syncthreads();  // previous compute done reading smem
            // Load Z tile: Zs[dd][tok] = in[b][d0+dd][hw0+tok]  (coalesced over tok)
#pragma unroll
            for (int i = tid; i < 2048; i += 256) {
                int dd = i >> 7;
                int t  = i & 127;
                Zs[dd][t] = inb[(size_t)(d0 + dd) * HW + t];
            }
            // Load E tile: Es[dd][c] = E[k0+c][d0+dd]  (16-float segments)
#pragma unroll
            for (int i = tid; i < 2048; i += 256) {
                int dd = i & 15;
                int c  = i >> 4;
                Es[dd][c] = E[(size_t)(k0 + c) * DIM + d0 + dd];
            }
            __syncthreads();

#pragma unroll
            for (int dd = 0; dd < 16; dd++) {
                float4 za = *(const float4*)&Zs[dd][ty * 8];
                float4 zb = *(const float4*)&Zs[dd][ty * 8 + 4];
                ulonglong2 ea = *(const ulonglong2*)&Es[dd][tx * 8];
                ulonglong2 eb = *(const ulonglong2*)&Es[dd][tx * 8 + 4];
                unsigned long long z2[8];
                z2[0] = pack2(za.x, za.x); z2[1] = pack2(za.y, za.y);
                z2[2] = pack2(za.z, za.z); z2[3] = pack2(za.w, za.w);
                z2[4] = pack2(zb.x, zb.x); z2[5] = pack2(zb.y, zb.y);
                z2[6] = pack2(zb.z, zb.z); z2[7] = pack2(zb.w, zb.w);
#pragma unroll
                for (int i = 0; i < 8; i++) {
                    ffma2(acc[i][0], z2[i], ea.x);
                    ffma2(acc[i][1], z2[i], ea.y);
                    ffma2(acc[i][2], z2[i], eb.x);
                    ffma2(acc[i][3], z2[i], eb.y);
                }
            }
        }

        // Epilogue: score = ||e||^2 - 2*dot ; running min (ascending idx keeps
        // first-match tie-break like jnp.argmin)
#pragma unroll
        for (int i = 0; i < 8; i++) {
#pragma unroll
            for (int jp = 0; jp < 4; jp++) {
                float2 f = unpack2(acc[i][jp]);
                int c0 = tx * 8 + jp * 2;
                float s0 = fmaf(-2.f, f.x, en_s[c0]);
                float s1 = fmaf(-2.f, f.y, en_s[c0 + 1]);
                if (s0 < best_val[i]) { best_val[i] = s0; best_idx[i] = k0 + c0; }
                if (s1 < best_val[i]) { best_val[i] = s1; best_idx[i] = k0 + c0 + 1; }
            }
        }
    }

    // Reduce across the 16 threads (one half-warp, same ty) that share rows.
#pragma unroll
    for (int i = 0; i < 8; i++) {
        float v = best_val[i];
        int   idx = best_idx[i];
#pragma unroll
        for (int off = 8; off > 0; off >>= 1) {
            float ov = __shfl_down_sync(0xffffffffu, v, off, 16);
            int   oi = __shfl_down_sync(0xffffffffu, idx, off, 16);
            if (ov < v || (ov == v && oi < idx)) { v = ov; idx = oi; }
        }
        if (tx == 0) g_kidx[b * HW + hw0 + ty * 8 + i] = idx;
    }
}

// ---------------- kernel 3: gather -> NCHW output + loss partial ---------------
// Grid: B*D = 16384 blocks, 256 threads. Coalesced in/out over hw; E reads are
// scattered but L2-resident (8MB codebook).
__global__ void gather_kernel(const float* __restrict__ in,
                              const float* __restrict__ E,
                              float* __restrict__ out) {
    int bd = blockIdx.x;
    int b = bd >> 9;
    int d = bd & 511;
    const int* kp = g_kidx + b * HW;
    size_t base = ((size_t)b * DIM + d) * HW;
    float local = 0.f;
#pragma unroll
    for (int it = 0; it < 4; it++) {
        int hw = it * 256 + threadIdx.x;
        int k = kp[hw];
        float e = E[(size_t)k * DIM + d];
        float z = in[base + hw];
        out[base + hw] = e;
        float df = z - e;
        local = fmaf(df, df, local);
    }
    __shared__ float red[256];
    red[threadIdx.x] = local;
    __syncthreads();
    for (int o = 128; o > 0; o >>= 1) {
        if (threadIdx.x < o) red[threadIdx.x] += red[threadIdx.x + o];
        __syncthreads();
    }
    if (threadIdx.x == 0) atomicAdd(&g_loss_acc, (double)red[0]);
}

// ---------------- kernel 4: final loss scalar ----------------------------------
__global__ void loss_kernel(float* __restrict__ out, int out_size) {
    if ((long long)out_size > TOTAL_OUT) {
        // loss = e_loss + 0.25*e_loss = 1.25 * mean((z - q)^2)
        double mean = g_loss_acc / (double)TOTAL_OUT;
        out[TOTAL_OUT] = (float)(1.25 * mean);
    }
}

// ---------------- launch --------------------------------------------------------
extern "C" void kernel_launch(void* const* d_in, const int* in_sizes, int n_in,
                              void* d_out, int out_size) {
    const float* in = (const float*)d_in[0];   // [32,512,32,32] fp32
    const float* E  = (const float*)d_in[1];   // [4096,512] fp32
    float* out = (float*)d_out;

    enorm_kernel<<<NCODE, 128>>>(E);
    argmin_kernel<<<NTOK / 128, 256>>>(in, E);
    gather_kernel<<<BATCH * DIM, 256>>>(in, E, out);
    loss_kernel<<<1, 1>>>(out, out_size);
}

// round 6
// speedup vs baseline: 2.9665x; 1.7846x over previous
#include <cuda_runtime.h>
#include <cuda_bf16.h>
#include <cstdint>

// Problem constants
#define BATCH 32
#define DIM   512
#define HW    1024
#define NTOK  (BATCH*HW)          // 32768
#define NCODE 4096
#define TOTAL_OUT ((long long)BATCH * DIM * HW)   // 16777216

// ---------------- device scratch (static; no runtime allocation) ---------------
// A' : 256 token-tiles x 16 chunks x (128x64 bf16 tile = 16KB = 1024 uint4) = 64MB
//      chunks 0..7 = hi(z) d-slices, 8..15 = lo(z).  Tile layout: row-major
//      128B rows with SW128 XOR swizzle (byte ^= (row&7)<<4 on bits[6:4]).
__device__ __align__(1024) uint4 g_A[256 * 16 * 1024];
// B' : 16 code-tiles(256 codes) x 16 chunks x (256x64 bf16 = 32KB = 2048 uint4) = 8MB
//      chunks 0..7 = hi(E), 8..15 = lo(E). Same swizzled row-major layout.
__device__ __align__(1024) uint4 g_B[16 * 16 * 2048];
__device__ float  g_enorm[NCODE];
__device__ int    g_kidx[NTOK];
__device__ double g_loss_acc;

// ---------------- PTX helpers (family-safe: sm_80-era instructions only) --------
__device__ __forceinline__ uint32_t smem_u32(const void* p) {
    uint32_t a;
    asm("{ .reg .u64 t; cvta.to.shared.u64 t, %1; cvt.u32.u64 %0, t; }"
        : "=r"(a) : "l"(p));
    return a;
}
__device__ __forceinline__ void cp16(uint32_t s, const void* g) {
    asm volatile("cp.async.cg.shared.global [%0], [%1], 16;"
                 :: "r"(s), "l"(g) : "memory");
}
#define CP_COMMIT() asm volatile("cp.async.commit_group;" ::: "memory")

__device__ __forceinline__ void ldm_x4(uint32_t* r, uint32_t addr) {
    asm volatile("ldmatrix.sync.aligned.m8n8.x4.shared.b16 {%0,%1,%2,%3}, [%4];"
                 : "=r"(r[0]), "=r"(r[1]), "=r"(r[2]), "=r"(r[3]) : "r"(addr));
}
__device__ __forceinline__ void mma16816(float* c, const uint32_t* a,
                                         uint32_t b0, uint32_t b1) {
    asm volatile(
        "mma.sync.aligned.m16n8k16.row.col.f32.bf16.bf16.f32 "
        "{%0,%1,%2,%3}, {%4,%5,%6,%7}, {%8,%9}, {%0,%1,%2,%3};"
        : "+f"(c[0]), "+f"(c[1]), "+f"(c[2]), "+f"(c[3])
        : "r"(a[0]), "r"(a[1]), "r"(a[2]), "r"(a[3]), "r"(b0), "r"(b1));
}

union Pack8 { uint4 v; __nv_bfloat16 h[8]; };

// ---------------- kernel 1: codebook norms + loss reset -------------------------
__global__ void enorm_kernel(const float* __restrict__ E) {
    __shared__ float red[128];
    int k = blockIdx.x;
    const float* row = E + (size_t)k * DIM;
    float s = 0.f;
    for (int d = threadIdx.x; d < DIM; d += 128) {
        float v = row[d];
        s = fmaf(v, v, s);
    }
    red[threadIdx.x] = s;
    __syncthreads();
    for (int o = 64; o > 0; o >>= 1) {
        if (threadIdx.x < o) red[threadIdx.x] += red[threadIdx.x + o];
        __syncthreads();
    }
    if (threadIdx.x == 0) g_enorm[k] = red[0];
    if (blockIdx.x == 0 && threadIdx.x == 0) g_loss_acc = 0.0;
}

// ---------------- kernel 2a: split z -> A' (pre-swizzled tiles) -----------------
// grid: 256 token-tiles x 16 chunks = 4096 blocks, 256 threads
__global__ void convA_kernel(const float* __restrict__ in) {
    int blk = blockIdx.x;
    int tt = blk >> 4;            // token tile (128 tokens)
    int ka = blk & 15;            // chunk
    int s  = ka >> 3;             // 0 = hi, 1 = lo
    int d0 = (ka & 7) * 64;
    int token0 = tt * 128;
    int b   = token0 >> 10;
    int hw0 = token0 & 1023;
#pragma unroll
    for (int i = 0; i < 4; i++) {
        int u  = threadIdx.x + 256 * i;   // unit = one uint4 = 8 bf16
        int cu = u >> 7;                  // 0..7  (8 cols of 8)
        int r  = u & 127;                 // token row
        const float* src = in + ((size_t)b * DIM + d0 + cu * 8) * HW + hw0 + r;
        Pack8 p;
#pragma unroll
        for (int j = 0; j < 8; j++) {
            float x = src[(size_t)j * HW];
            __nv_bfloat16 h = __float2bfloat16(x);
            p.h[j] = s ? __float2bfloat16(x - __bfloat162float(h)) : h;
        }
        int byte = r * 128 + (cu << 4);
        int sw = byte ^ ((byte >> 3) & 0x70);
        g_A[((size_t)blk << 10) + (sw >> 4)] = p.v;
    }
}

// ---------------- kernel 2b: split E -> B' --------------------------------------
// grid: 16 code-tiles x 16 chunks = 256 blocks, 256 threads
__global__ void convB_kernel(const float* __restrict__ E) {
    int blk = blockIdx.x;
    int nt = blk >> 4;
    int kb = blk & 15;
    int s  = kb >> 3;             // 0 = hi, 1 = lo
    int d0 = (kb & 7) * 64;
#pragma unroll
    for (int i = 0; i < 8; i++) {
        int u  = threadIdx.x + 256 * i;   // 2048 units
        int cu = u & 7;
        int r  = u >> 3;                  // code row 0..255
        const float* src = E + (size_t)(nt * 256 + r) * DIM + d0 + cu * 8;
        Pack8 p;
#pragma unroll
        for (int j = 0; j < 8; j++) {
            float x = src[j];
            __nv_bfloat16 h = __float2bfloat16(x);
            p.h[j] = s ? __float2bfloat16(x - __bfloat162float(h)) : h;
        }
        int byte = r * 128 + (cu << 4);
        int sw = byte ^ ((byte >> 3) & 0x70);
        g_B[((size_t)blk << 11) + (sw >> 4)] = p.v;
    }
}

// ---------------- kernel 3: mma.sync GEMM + fused argmin ------------------------
// 128 CTAs x 512 threads. CTA: M=256 tokens, sweep 32 N-tiles of 128 codes.
// Per d-slice (64 dims): load {Ah,Al,Bh,Bl} (96KB) once, compute 3 split-bf16
// products (zh*eh + zl*eh + zh*el). 2-stage cp.async pipeline over the
// (ntile, slice) stream of 256 steps.
#define STAGE_BYTES 98304
#define SMEM_DYN    (2 * STAGE_BYTES)

__global__ __launch_bounds__(512, 1) void vq_mma_kernel() {
    extern __shared__ __align__(128) char dsm[];
    __shared__ float sval[256][2];
    __shared__ int   sidx[256][2];

    const uint32_t sbase = smem_u32(dsm);
    const int tid  = threadIdx.x;
    const int wid  = tid >> 5;
    const int lane = tid & 31;
    const int wm   = wid >> 1;          // 0..7 : rows wm*32
    const int wn   = wid & 1;           // 0..1 : cols wn*64
    const int cb   = blockIdx.x;

    // per-lane ldmatrix swizzled address components
    const int rowA = wm * 32 + (lane & 15);
    const uint32_t offA = (uint32_t)(rowA * 128 + ((lane >> 4) * 8) * 2);
    const uint32_t xorA = (uint32_t)((rowA & 7) << 4);
    const int rowB = wn * 64 + (lane & 7) + ((lane & 16) ? 8 : 0);
    const uint32_t offB = (uint32_t)(rowB * 128 + (((lane >> 3) & 1) * 8) * 2);
    const uint32_t xorB = (uint32_t)((rowB & 7) << 4);

    float acc[2][8][4];
#pragma unroll
    for (int fm = 0; fm < 2; fm++)
#pragma unroll
        for (int nf = 0; nf < 8; nf++)
#pragma unroll
            for (int j = 0; j < 4; j++) acc[fm][nf][j] = 0.f;

    float best[4];
    int   bidx[4];
#pragma unroll
    for (int r = 0; r < 4; r++) { best[r] = 3.4e38f; bidx[r] = 0; }

    // -------- load slice t of the (ntile, slice) stream into stage t&1 --------
    auto issue_load = [&](int t) {
        const int nt128 = t >> 3;
        const int s     = t & 7;
        const uint32_t dst = sbase + (uint32_t)(t & 1) * STAGE_BYTES;
        const uint4* Ah0 = g_A + (((size_t)(2 * cb) * 16 + s) << 10);
        const uint4* Ah1 = Ah0 + (16 << 10);
        const uint4* Al0 = Ah0 + (8 << 10);
        const uint4* Al1 = Ah1 + (8 << 10);
        const uint4* Bh  = g_B + (((size_t)(nt128 >> 1) * 16 + s) << 11)
                               + (nt128 & 1) * 1024;
        const uint4* Bl  = Bh + (8 << 11);
#pragma unroll
        for (int i = 0; i < 2; i++) {
            int u = tid + 512 * i;
            cp16(dst + u * 16, Ah0 + u);                    // Ah rows 0-127
            cp16(dst + 16384 + u * 16, Ah1 + u);            // Ah rows 128-255
            cp16(dst + 32768 + u * 16, Al0 + u);            // Al rows 0-127
            cp16(dst + 49152 + u * 16, Al1 + u);            // Al rows 128-255
        }
#pragma unroll
        for (int i = 0; i < 2; i++) {
            int u = tid + 512 * i;
            cp16(dst + 65536 + u * 16, Bh + u);             // Bh 128 codes
            cp16(dst + 81920 + u * 16, Bl + u);             // Bl 128 codes
        }
        CP_COMMIT();
    };

    issue_load(0);

    for (int t = 0; t < 256; t++) {
        if (t < 255) {
            issue_load(t + 1);
            asm volatile("cp.async.wait_group 1;" ::: "memory");
        } else {
            asm volatile("cp.async.wait_group 0;" ::: "memory");
        }
        __syncthreads();

        const uint32_t base = sbase + (uint32_t)(t & 1) * STAGE_BYTES;
        // 3 products: (Ah,Bh), (Al,Bh), (Ah,Bl)
#pragma unroll
        for (int p = 0; p < 3; p++) {
            const uint32_t Ab = base + ((p == 1) ? 32768u : 0u);
            const uint32_t Bb = base + ((p == 2) ? 81920u : 65536u);
#pragma unroll
            for (int k16 = 0; k16 < 4; k16++) {
                uint32_t a[2][4];
#pragma unroll
                for (int fm = 0; fm < 2; fm++)
                    ldm_x4(a[fm], Ab + ((offA + fm * 2048 + k16 * 32) ^ xorA));
                uint32_t b[4][4];
#pragma unroll
                for (int n4 = 0; n4 < 4; n4++)
                    ldm_x4(b[n4], Bb + ((offB + n4 * 2048 + k16 * 32) ^ xorB));
#pragma unroll
                for (int fm = 0; fm < 2; fm++)
#pragma unroll
                    for (int n4 = 0; n4 < 4; n4++) {
                        mma16816(acc[fm][n4 * 2],     a[fm], b[n4][0], b[n4][1]);
                        mma16816(acc[fm][n4 * 2 + 1], a[fm], b[n4][2], b[n4][3]);
                    }
            }
        }

        // ------- epilogue after last slice of each N-tile: score + argmin -------
        if ((t & 7) == 7) {
            const int nt128 = t >> 3;
            const int colbase = nt128 * 128 + wn * 64 + (lane & 3) * 2;
#pragma unroll
            for (int nf = 0; nf < 8; nf++) {
                const int c0 = colbase + nf * 8;
                const float e0 = g_enorm[c0];
                const float e1 = g_enorm[c0 + 1];
#pragma unroll
                for (int fm = 0; fm < 2; fm++) {
                    float v0 = fmaf(-2.f, acc[fm][nf][0], e0);
                    float v1 = fmaf(-2.f, acc[fm][nf][1], e1);
                    float v2 = fmaf(-2.f, acc[fm][nf][2], e0);
                    float v3 = fmaf(-2.f, acc[fm][nf][3], e1);
                    if (v0 < best[fm * 2])     { best[fm * 2] = v0;     bidx[fm * 2] = c0; }
                    if (v1 < best[fm * 2])     { best[fm * 2] = v1;     bidx[fm * 2] = c0 + 1; }
                    if (v2 < best[fm * 2 + 1]) { best[fm * 2 + 1] = v2; bidx[fm * 2 + 1] = c0; }
                    if (v3 < best[fm * 2 + 1]) { best[fm * 2 + 1] = v3; bidx[fm * 2 + 1] = c0 + 1; }
                    acc[fm][nf][0] = 0.f; acc[fm][nf][1] = 0.f;
                    acc[fm][nf][2] = 0.f; acc[fm][nf][3] = 0.f;
                }
            }
        }
        __syncthreads();   // buffer t+1's slot free before next issue_load
    }

    // ---------------- final cross-thread argmin reduce --------------------------
#pragma unroll
    for (int r = 0; r < 4; r++) {
        float v = best[r];
        int   ix = bidx[r];
#pragma unroll
        for (int o = 1; o < 4; o <<= 1) {
            float ov = __shfl_xor_sync(0xffffffffu, v, o);
            int   oi = __shfl_xor_sync(0xffffffffu, ix, o);
            if (ov < v || (ov == v && oi < ix)) { v = ov; ix = oi; }
        }
        if ((lane & 3) == 0) {
            int fm = r >> 1, h = r & 1;
            int R = wm * 32 + fm * 16 + h * 8 + (lane >> 2);
            sval[R][wn] = v;
            sidx[R][wn] = ix;
        }
    }
    __syncthreads();
    if (tid < 256) {
        float v0 = sval[tid][0], v1 = sval[tid][1];
        int   i0 = sidx[tid][0], i1 = sidx[tid][1];
        g_kidx[cb * 256 + tid] = (v1 < v0 || (v1 == v0 && i1 < i0)) ? i1 : i0;
    }
}

// ---------------- kernel 4: gather -> NCHW output + loss partial ----------------
__global__ void gather_kernel(const float* __restrict__ in,
                              const float* __restrict__ E,
                              float* __restrict__ out) {
    int bd = blockIdx.x;
    int b = bd >> 9;
    int d = bd & 511;
    const int* kp = g_kidx + b * HW;
    size_t base = ((size_t)b * DIM + d) * HW;
    float local = 0.f;
#pragma unroll
    for (int it = 0; it < 4; it++) {
        int hw = it * 256 + threadIdx.x;
        int k = kp[hw];
        float e = E[(size_t)k * DIM + d];
        float z = in[base + hw];
        out[base + hw] = e;
        float df = z - e;
        local = fmaf(df, df, local);
    }
    __shared__ float red[256];
    red[threadIdx.x] = local;
    __syncthreads();
    for (int o = 128; o > 0; o >>= 1) {
        if (threadIdx.x < o) red[threadIdx.x] += red[threadIdx.x + o];
        __syncthreads();
    }
    if (threadIdx.x == 0) atomicAdd(&g_loss_acc, (double)red[0]);
}

// ---------------- kernel 5: final loss scalar -----------------------------------
__global__ void loss_kernel(float* __restrict__ out, int out_size) {
    if ((long long)out_size > TOTAL_OUT) {
        double mean = g_loss_acc / (double)TOTAL_OUT;
        out[TOTAL_OUT] = (float)(1.25 * mean);
    }
}

// ---------------- launch --------------------------------------------------------
extern "C" void kernel_launch(void* const* d_in, const int* in_sizes, int n_in,
                              void* d_out, int out_size) {
    const float* in = (const float*)d_in[0];   // [32,512,32,32] fp32
    const float* E  = (const float*)d_in[1];   // [4096,512] fp32
    float* out = (float*)d_out;

    cudaFuncSetAttribute(vq_mma_kernel,
                         cudaFuncAttributeMaxDynamicSharedMemorySize, SMEM_DYN);

    enorm_kernel<<<NCODE, 128>>>(E);
    convA_kernel<<<256 * 16, 256>>>(in);
    convB_kernel<<<16 * 16, 256>>>(E);
    vq_mma_kernel<<<128, 512, SMEM_DYN>>>();
    gather_kernel<<<BATCH * DIM, 256>>>(in, E, out);
    loss_kernel<<<1, 1>>>(out, out_size);
}

// round 11
// speedup vs baseline: 4.9362x; 1.6640x over previous
#include <cuda_runtime.h>
#include <cuda_bf16.h>
#include <cstdint>

// Problem constants
#define BATCH 32
#define DIM   512
#define HW    1024
#define NTOK  (BATCH*HW)          // 32768
#define NCODE 4096
#define TOTAL_OUT ((long long)BATCH * DIM * HW)   // 16777216

// ---------------- device scratch (static; no runtime allocation) ---------------
// A' : 256 token-tiles x 16 chunks x (128x64 bf16 tile = 16KB = 1024 uint4) = 64MB
//      chunks 0..7 = hi(z) d-slices, 8..15 = lo(z).  Tile layout: row-major
//      128B rows with SW128 XOR swizzle (byte ^= (row&7)<<4 on bits[6:4]).
__device__ __align__(1024) uint4 g_A[256 * 16 * 1024];
// B' : 16 code-tiles(256 codes) x 16 chunks x (256x64 bf16 = 32KB = 2048 uint4) = 8MB
//      chunks 0..7 = hi(E), 8..15 = lo(E). Same swizzled row-major layout.
__device__ __align__(1024) uint4 g_B[16 * 16 * 2048];
__device__ float  g_enorm[NCODE];
__device__ int    g_kidx[NTOK];
__device__ double g_loss_acc;

// ---------------- PTX helpers (family-safe: sm_80-era instructions only) --------
__device__ __forceinline__ uint32_t smem_u32(const void* p) {
    uint32_t a;
    asm("{ .reg .u64 t; cvta.to.shared.u64 t, %1; cvt.u32.u64 %0, t; }"
        : "=r"(a) : "l"(p));
    return a;
}
__device__ __forceinline__ void cp16(uint32_t s, const void* g) {
    asm volatile("cp.async.cg.shared.global [%0], [%1], 16;"
                 :: "r"(s), "l"(g) : "memory");
}
#define CP_COMMIT() asm volatile("cp.async.commit_group;" ::: "memory")

__device__ __forceinline__ void ldm_x4(uint32_t* r, uint32_t addr) {
    asm volatile("ldmatrix.sync.aligned.m8n8.x4.shared.b16 {%0,%1,%2,%3}, [%4];"
                 : "=r"(r[0]), "=r"(r[1]), "=r"(r[2]), "=r"(r[3]) : "r"(addr));
}
__device__ __forceinline__ void mma16816(float* c, const uint32_t* a,
                                         uint32_t b0, uint32_t b1) {
    asm volatile(
        "mma.sync.aligned.m16n8k16.row.col.f32.bf16.bf16.f32 "
        "{%0,%1,%2,%3}, {%4,%5,%6,%7}, {%8,%9}, {%0,%1,%2,%3};"
        : "+f"(c[0]), "+f"(c[1]), "+f"(c[2]), "+f"(c[3])
        : "r"(a[0]), "r"(a[1]), "r"(a[2]), "r"(a[3]), "r"(b0), "r"(b1));
}

union Pack8 { uint4 v; __nv_bfloat16 h[8]; };

// ---------------- kernel 1: codebook norms + loss reset -------------------------
__global__ void enorm_kernel(const float* __restrict__ E) {
    __shared__ float red[128];
    int k = blockIdx.x;
    const float* row = E + (size_t)k * DIM;
    float s = 0.f;
    for (int d = threadIdx.x; d < DIM; d += 128) {
        float v = row[d];
        s = fmaf(v, v, s);
    }
    red[threadIdx.x] = s;
    __syncthreads();
    for (int o = 64; o > 0; o >>= 1) {
        if (threadIdx.x < o) red[threadIdx.x] += red[threadIdx.x + o];
        __syncthreads();
    }
    if (threadIdx.x == 0) g_enorm[k] = red[0];
    if (blockIdx.x == 0 && threadIdx.x == 0) g_loss_acc = 0.0;
}

// ---------------- kernel 2a: split z -> A' (pre-swizzled tiles) -----------------
// grid: 256 token-tiles x 16 chunks = 4096 blocks, 256 threads
__global__ void convA_kernel(const float* __restrict__ in) {
    int blk = blockIdx.x;
    int tt = blk >> 4;            // token tile (128 tokens)
    int ka = blk & 15;            // chunk
    int s  = ka >> 3;             // 0 = hi, 1 = lo
    int d0 = (ka & 7) * 64;
    int token0 = tt * 128;
    int b   = token0 >> 10;
    int hw0 = token0 & 1023;
#pragma unroll
    for (int i = 0; i < 4; i++) {
        int u  = threadIdx.x + 256 * i;   // unit = one uint4 = 8 bf16
        int cu = u >> 7;                  // 0..7  (8 cols of 8)
        int r  = u & 127;                 // token row
        const float* src = in + ((size_t)b * DIM + d0 + cu * 8) * HW + hw0 + r;
        Pack8 p;
#pragma unroll
        for (int j = 0; j < 8; j++) {
            float x = src[(size_t)j * HW];
            __nv_bfloat16 h = __float2bfloat16(x);
            p.h[j] = s ? __float2bfloat16(x - __bfloat162float(h)) : h;
        }
        int byte = r * 128 + (cu << 4);
        int sw = byte ^ ((byte >> 3) & 0x70);
        g_A[((size_t)blk << 10) + (sw >> 4)] = p.v;
    }
}

// ---------------- kernel 2b: split E -> B' --------------------------------------
// grid: 16 code-tiles x 16 chunks = 256 blocks, 256 threads
__global__ void convB_kernel(const float* __restrict__ E) {
    int blk = blockIdx.x;
    int nt = blk >> 4;
    int kb = blk & 15;
    int s  = kb >> 3;             // 0 = hi, 1 = lo
    int d0 = (kb & 7) * 64;
#pragma unroll
    for (int i = 0; i < 8; i++) {
        int u  = threadIdx.x + 256 * i;   // 2048 units
        int cu = u & 7;
        int r  = u >> 3;                  // code row 0..255
        const float* src = E + (size_t)(nt * 256 + r) * DIM + d0 + cu * 8;
        Pack8 p;
#pragma unroll
        for (int j = 0; j < 8; j++) {
            float x = src[j];
            __nv_bfloat16 h = __float2bfloat16(x);
            p.h[j] = s ? __float2bfloat16(x - __bfloat162float(h)) : h;
        }
        int byte = r * 128 + (cu << 4);
        int sw = byte ^ ((byte >> 3) & 0x70);
        g_B[((size_t)blk << 11) + (sw >> 4)] = p.v;
    }
}

// ---------------- kernel 3: mma.sync GEMM + fused argmin ------------------------
// 128 CTAs x 512 threads. CTA: M=256 tokens, sweep 32 N-tiles of 128 codes.
// Per d-slice (64 dims): load {Ah,Al,Bh,Bl} (96KB) once, compute 3 split-bf16
// products (zh*eh + zl*eh + zh*el). 2-stage cp.async pipeline over the
// (ntile, slice) stream of 256 steps.
// Register-reuse compute loop: per k16 load aH,aL once; per n4 load bh,bl once
// and issue all 12 MMAs that touch them (12 ldm / 48 mma per k16, was 18/48).
#define STAGE_BYTES 98304
#define SMEM_DYN    (2 * STAGE_BYTES)

__global__ __launch_bounds__(512, 1) void vq_mma_kernel() {
    extern __shared__ __align__(128) char dsm[];
    __shared__ float sval[256][2];
    __shared__ int   sidx[256][2];

    const uint32_t sbase = smem_u32(dsm);
    const int tid  = threadIdx.x;
    const int wid  = tid >> 5;
    const int lane = tid & 31;
    const int wm   = wid >> 1;          // 0..7 : rows wm*32
    const int wn   = wid & 1;           // 0..1 : cols wn*64
    const int cb   = blockIdx.x;

    // per-lane ldmatrix swizzled address components
    const int rowA = wm * 32 + (lane & 15);
    const uint32_t offA = (uint32_t)(rowA * 128 + ((lane >> 4) * 8) * 2);
    const uint32_t xorA = (uint32_t)((rowA & 7) << 4);
    const int rowB = wn * 64 + (lane & 7) + ((lane & 16) ? 8 : 0);
    const uint32_t offB = (uint32_t)(rowB * 128 + (((lane >> 3) & 1) * 8) * 2);
    const uint32_t xorB = (uint32_t)((rowB & 7) << 4);

    float acc[2][8][4];
#pragma unroll
    for (int fm = 0; fm < 2; fm++)
#pragma unroll
        for (int nf = 0; nf < 8; nf++)
#pragma unroll
            for (int j = 0; j < 4; j++) acc[fm][nf][j] = 0.f;

    float best[4];
    int   bidx[4];
#pragma unroll
    for (int r = 0; r < 4; r++) { best[r] = 3.4e38f; bidx[r] = 0; }

    // -------- load slice t of the (ntile, slice) stream into stage t&1 --------
    auto issue_load = [&](int t) {
        const int nt128 = t >> 3;
        const int s     = t & 7;
        const uint32_t dst = sbase + (uint32_t)(t & 1) * STAGE_BYTES;
        const uint4* Ah0 = g_A + (((size_t)(2 * cb) * 16 + s) << 10);
        const uint4* Ah1 = Ah0 + (16 << 10);
        const uint4* Al0 = Ah0 + (8 << 10);
        const uint4* Al1 = Ah1 + (8 << 10);
        const uint4* Bh  = g_B + (((size_t)(nt128 >> 1) * 16 + s) << 11)
                               + (nt128 & 1) * 1024;
        const uint4* Bl  = Bh + (8 << 11);
#pragma unroll
        for (int i = 0; i < 2; i++) {
            int u = tid + 512 * i;
            cp16(dst + u * 16, Ah0 + u);                    // Ah rows 0-127
            cp16(dst + 16384 + u * 16, Ah1 + u);            // Ah rows 128-255
            cp16(dst + 32768 + u * 16, Al0 + u);            // Al rows 0-127
            cp16(dst + 49152 + u * 16, Al1 + u);            // Al rows 128-255
        }
#pragma unroll
        for (int i = 0; i < 2; i++) {
            int u = tid + 512 * i;
            cp16(dst + 65536 + u * 16, Bh + u);             // Bh 128 codes
            cp16(dst + 81920 + u * 16, Bl + u);             // Bl 128 codes
        }
        CP_COMMIT();
    };

    issue_load(0);

    for (int t = 0; t < 256; t++) {
        if (t < 255) {
            issue_load(t + 1);
            asm volatile("cp.async.wait_group 1;" ::: "memory");
        } else {
            asm volatile("cp.async.wait_group 0;" ::: "memory");
        }
        __syncthreads();

        const uint32_t base = sbase + (uint32_t)(t & 1) * STAGE_BYTES;
#pragma unroll
        for (int k16 = 0; k16 < 4; k16++) {
            // A fragments for this k16: hi and lo, both M-halves.
            uint32_t aH[2][4], aL[2][4];
#pragma unroll
            for (int fm = 0; fm < 2; fm++) {
                ldm_x4(aH[fm], base + ((offA + fm * 2048 + k16 * 32) ^ xorA));
                ldm_x4(aL[fm], base + 32768u + ((offA + fm * 2048 + k16 * 32) ^ xorA));
            }
#pragma unroll
            for (int n4 = 0; n4 < 4; n4++) {
                uint32_t bh[4];
                ldm_x4(bh, base + 65536u + ((offB + n4 * 2048 + k16 * 32) ^ xorB));
#pragma unroll
                for (int fm = 0; fm < 2; fm++) {
                    mma16816(acc[fm][n4 * 2],     aH[fm], bh[0], bh[1]);
                    mma16816(acc[fm][n4 * 2 + 1], aH[fm], bh[2], bh[3]);
                    mma16816(acc[fm][n4 * 2],     aL[fm], bh[0], bh[1]);
                    mma16816(acc[fm][n4 * 2 + 1], aL[fm], bh[2], bh[3]);
                }
                uint32_t bl[4];
                ldm_x4(bl, base + 81920u + ((offB + n4 * 2048 + k16 * 32) ^ xorB));
#pragma unroll
                for (int fm = 0; fm < 2; fm++) {
                    mma16816(acc[fm][n4 * 2],     aH[fm], bl[0], bl[1]);
                    mma16816(acc[fm][n4 * 2 + 1], aH[fm], bl[2], bl[3]);
                }
            }
        }

        // ------- epilogue after last slice of each N-tile: score + argmin -------
        if ((t & 7) == 7) {
            const int nt128 = t >> 3;
            const int colbase = nt128 * 128 + wn * 64 + (lane & 3) * 2;
#pragma unroll
            for (int nf = 0; nf < 8; nf++) {
                const int c0 = colbase + nf * 8;
                const float e0 = g_enorm[c0];
                const float e1 = g_enorm[c0 + 1];
#pragma unroll
                for (int fm = 0; fm < 2; fm++) {
                    float v0 = fmaf(-2.f, acc[fm][nf][0], e0);
                    float v1 = fmaf(-2.f, acc[fm][nf][1], e1);
                    float v2 = fmaf(-2.f, acc[fm][nf][2], e0);
                    float v3 = fmaf(-2.f, acc[fm][nf][3], e1);
                    if (v0 < best[fm * 2])     { best[fm * 2] = v0;     bidx[fm * 2] = c0; }
                    if (v1 < best[fm * 2])     { best[fm * 2] = v1;     bidx[fm * 2] = c0 + 1; }
                    if (v2 < best[fm * 2 + 1]) { best[fm * 2 + 1] = v2; bidx[fm * 2 + 1] = c0; }
                    if (v3 < best[fm * 2 + 1]) { best[fm * 2 + 1] = v3; bidx[fm * 2 + 1] = c0 + 1; }
                    acc[fm][nf][0] = 0.f; acc[fm][nf][1] = 0.f;
                    acc[fm][nf][2] = 0.f; acc[fm][nf][3] = 0.f;
                }
            }
        }
        __syncthreads();   // buffer t+1's slot free before next issue_load
    }

    // ---------------- final cross-thread argmin reduce --------------------------
#pragma unroll
    for (int r = 0; r < 4; r++) {
        float v = best[r];
        int   ix = bidx[r];
#pragma unroll
        for (int o = 1; o < 4; o <<= 1) {
            float ov = __shfl_xor_sync(0xffffffffu, v, o);
            int   oi = __shfl_xor_sync(0xffffffffu, ix, o);
            if (ov < v || (ov == v && oi < ix)) { v = ov; ix = oi; }
        }
        if ((lane & 3) == 0) {
            int fm = r >> 1, h = r & 1;
            int R = wm * 32 + fm * 16 + h * 8 + (lane >> 2);
            sval[R][wn] = v;
            sidx[R][wn] = ix;
        }
    }
    __syncthreads();
    if (tid < 256) {
        float v0 = sval[tid][0], v1 = sval[tid][1];
        int   i0 = sidx[tid][0], i1 = sidx[tid][1];
        g_kidx[cb * 256 + tid] = (v1 < v0 || (v1 == v0 && i1 < i0)) ? i1 : i0;
    }
}

// ---------------- kernel 4: gather -> NCHW output + loss partial ----------------
__global__ void gather_kernel(const float* __restrict__ in,
                              const float* __restrict__ E,
                              float* __restrict__ out) {
    int bd = blockIdx.x;
    int b = bd >> 9;
    int d = bd & 511;
    const int* kp = g_kidx + b * HW;
    size_t base = ((size_t)b * DIM + d) * HW;
    float local = 0.f;
#pragma unroll
    for (int it = 0; it < 4; it++) {
        int hw = it * 256 + threadIdx.x;
        int k = kp[hw];
        float e = E[(size_t)k * DIM + d];
        float z = in[base + hw];
        out[base + hw] = e;
        float df = z - e;
        local = fmaf(df, df, local);
    }
    __shared__ float red[256];
    red[threadIdx.x] = local;
    __syncthreads();
    for (int o = 128; o > 0; o >>= 1) {
        if (threadIdx.x < o) red[threadIdx.x] += red[threadIdx.x + o];
        __syncthreads();
    }
    if (threadIdx.x == 0) atomicAdd(&g_loss_acc, (double)red[0]);
}

// ---------------- kernel 5: final loss scalar -----------------------------------
__global__ void loss_kernel(float* __restrict__ out, int out_size) {
    if ((long long)out_size > TOTAL_OUT) {
        double mean = g_loss_acc / (double)TOTAL_OUT;
        out[TOTAL_OUT] = (float)(1.25 * mean);
    }
}

// ---------------- launch --------------------------------------------------------
extern "C" void kernel_launch(void* const* d_in, const int* in_sizes, int n_in,
                              void* d_out, int out_size) {
    const float* in = (const float*)d_in[0];   // [32,512,32,32] fp32
    const float* E  = (const float*)d_in[1];   // [4096,512] fp32
    float* out = (float*)d_out;

    cudaFuncSetAttribute(vq_mma_kernel,
                         cudaFuncAttributeMaxDynamicSharedMemorySize, SMEM_DYN);

    enorm_kernel<<<NCODE, 128>>>(E);
    convA_kernel<<<256 * 16, 256>>>(in);
    convB_kernel<<<16 * 16, 256>>>(E);
    vq_mma_kernel<<<128, 512, SMEM_DYN>>>();
    gather_kernel<<<BATCH * DIM, 256>>>(in, E, out);
    loss_kernel<<<1, 1>>>(out, out_size);
}

// round 13
// speedup vs baseline: 5.4627x; 1.1067x over previous
#include <cuda_runtime.h>
#include <cuda_bf16.h>
#include <cstdint>

// Problem constants
#define BATCH 32
#define DIM   512
#define HW    1024
#define NTOK  (BATCH*HW)          // 32768
#define NCODE 4096
#define TOTAL_OUT ((long long)BATCH * DIM * HW)   // 16777216

#define GRID_MMA 152              // one CTA per GB300 SM
#define NUNITS   1024             // (256 tokens x 512 codes) work units

// ---------------- device scratch (static; no runtime allocation) ---------------
// A' : 256 token-tiles x 16 chunks x (128x64 bf16 tile = 16KB = 1024 uint4) = 64MB
//      chunks 0..7 = hi(z) d-slices, 8..15 = lo(z).  Tile layout: row-major
//      128B rows with SW128 XOR swizzle (byte ^= (row&7)<<4 on bits[6:4]).
__device__ __align__(1024) uint4 g_A[256 * 16 * 1024];
// B' : 16 code-tiles(256 codes) x 16 chunks x (256x64 bf16 = 32KB = 2048 uint4) = 8MB
//      chunks 0..7 = hi(E), 8..15 = lo(E). Same swizzled row-major layout.
__device__ __align__(1024) uint4 g_B[16 * 16 * 2048];
__device__ float  g_enorm[NCODE];
__device__ unsigned long long g_best[NTOK];   // packed (ordered_score<<32)|idx
__device__ double g_loss_acc;

// ---------------- PTX helpers (family-safe: sm_80-era instructions only) --------
__device__ __forceinline__ uint32_t smem_u32(const void* p) {
    uint32_t a;
    asm("{ .reg .u64 t; cvta.to.shared.u64 t, %1; cvt.u32.u64 %0, t; }"
        : "=r"(a) : "l"(p));
    return a;
}
__device__ __forceinline__ void cp16(uint32_t s, const void* g) {
    asm volatile("cp.async.cg.shared.global [%0], [%1], 16;"
                 :: "r"(s), "l"(g) : "memory");
}
#define CP_COMMIT() asm volatile("cp.async.commit_group;" ::: "memory")

__device__ __forceinline__ void ldm_x4(uint32_t* r, uint32_t addr) {
    asm volatile("ldmatrix.sync.aligned.m8n8.x4.shared.b16 {%0,%1,%2,%3}, [%4];"
                 : "=r"(r[0]), "=r"(r[1]), "=r"(r[2]), "=r"(r[3]) : "r"(addr));
}
__device__ __forceinline__ void mma16816(float* c, const uint32_t* a,
                                         uint32_t b0, uint32_t b1) {
    asm volatile(
        "mma.sync.aligned.m16n8k16.row.col.f32.bf16.bf16.f32 "
        "{%0,%1,%2,%3}, {%4,%5,%6,%7}, {%8,%9}, {%0,%1,%2,%3};"
        : "+f"(c[0]), "+f"(c[1]), "+f"(c[2]), "+f"(c[3])
        : "r"(a[0]), "r"(a[1]), "r"(a[2]), "r"(a[3]), "r"(b0), "r"(b1));
}

// monotone float -> uint32 key (preserves <, equal floats -> equal keys)
__device__ __forceinline__ uint32_t fkey(float v) {
    uint32_t u = __float_as_uint(v);
    return (u & 0x80000000u) ? ~u : (u | 0x80000000u);
}

union Pack8 { uint4 v; __nv_bfloat16 h[8]; };

// ---------------- kernel 0: init packed-best + loss reset -----------------------
__global__ void init_kernel() {
    int i = blockIdx.x * 256 + threadIdx.x;
    g_best[i] = 0xFFFFFFFFFFFFFFFFULL;
    if (i == 0) g_loss_acc = 0.0;
}

// ---------------- kernel 1: codebook norms --------------------------------------
__global__ void enorm_kernel(const float* __restrict__ E) {
    __shared__ float red[128];
    int k = blockIdx.x;
    const float* row = E + (size_t)k * DIM;
    float s = 0.f;
    for (int d = threadIdx.x; d < DIM; d += 128) {
        float v = row[d];
        s = fmaf(v, v, s);
    }
    red[threadIdx.x] = s;
    __syncthreads();
    for (int o = 64; o > 0; o >>= 1) {
        if (threadIdx.x < o) red[threadIdx.x] += red[threadIdx.x + o];
        __syncthreads();
    }
    if (threadIdx.x == 0) g_enorm[k] = red[0];
}

// ---------------- kernel 2a: split z -> A' (pre-swizzled tiles) -----------------
// grid: 256 token-tiles x 16 chunks = 4096 blocks, 256 threads
__global__ void convA_kernel(const float* __restrict__ in) {
    int blk = blockIdx.x;
    int tt = blk >> 4;            // token tile (128 tokens)
    int ka = blk & 15;            // chunk
    int s  = ka >> 3;             // 0 = hi, 1 = lo
    int d0 = (ka & 7) * 64;
    int token0 = tt * 128;
    int b   = token0 >> 10;
    int hw0 = token0 & 1023;
#pragma unroll
    for (int i = 0; i < 4; i++) {
        int u  = threadIdx.x + 256 * i;   // unit = one uint4 = 8 bf16
        int cu = u >> 7;                  // 0..7  (8 cols of 8)
        int r  = u & 127;                 // token row
        const float* src = in + ((size_t)b * DIM + d0 + cu * 8) * HW + hw0 + r;
        Pack8 p;
#pragma unroll
        for (int j = 0; j < 8; j++) {
            float x = src[(size_t)j * HW];
            __nv_bfloat16 h = __float2bfloat16(x);
            p.h[j] = s ? __float2bfloat16(x - __bfloat162float(h)) : h;
        }
        int byte = r * 128 + (cu << 4);
        int sw = byte ^ ((byte >> 3) & 0x70);
        g_A[((size_t)blk << 10) + (sw >> 4)] = p.v;
    }
}

// ---------------- kernel 2b: split E -> B' --------------------------------------
// grid: 16 code-tiles x 16 chunks = 256 blocks, 256 threads
__global__ void convB_kernel(const float* __restrict__ E) {
    int blk = blockIdx.x;
    int nt = blk >> 4;
    int kb = blk & 15;
    int s  = kb >> 3;             // 0 = hi, 1 = lo
    int d0 = (kb & 7) * 64;
#pragma unroll
    for (int i = 0; i < 8; i++) {
        int u  = threadIdx.x + 256 * i;   // 2048 units
        int cu = u & 7;
        int r  = u >> 3;                  // code row 0..255
        const float* src = E + (size_t)(nt * 256 + r) * DIM + d0 + cu * 8;
        Pack8 p;
#pragma unroll
        for (int j = 0; j < 8; j++) {
            float x = src[j];
            __nv_bfloat16 h = __float2bfloat16(x);
            p.h[j] = s ? __float2bfloat16(x - __bfloat162float(h)) : h;
        }
        int byte = r * 128 + (cu << 4);
        int sw = byte ^ ((byte >> 3) & 0x70);
        g_B[((size_t)blk << 11) + (sw >> 4)] = p.v;
    }
}

// ---------------- kernel 3: mma.sync GEMM + fused argmin ------------------------
// Persistent distribution: 152 CTAs x 512 threads over 1024 units of
// (256 tokens x 512 codes); CTA b takes units b, b+152, ...  Each unit is
// 4 N-tiles(128 codes) x 8 d-slices = 32 pipeline steps. Per step load
// {Ah,Al,Bh,Bl} (96KB) via cp.async double buffer, compute 3 split-bf16
// products (zh*eh + zl*eh + zh*el). At unit end, per-token argmin candidates
// merge globally via atomicMin on (ordered_score<<32)|idx.
#define STAGE_BYTES 98304
#define SMEM_DYN    (2 * STAGE_BYTES)

__global__ __launch_bounds__(512, 1) void vq_mma_kernel() {
    extern __shared__ __align__(128) char dsm[];
    __shared__ float sval[256][2];
    __shared__ int   sidx[256][2];

    const uint32_t sbase = smem_u32(dsm);
    const int tid  = threadIdx.x;
    const int wid  = tid >> 5;
    const int lane = tid & 31;
    const int wm   = wid >> 1;          // 0..7 : rows wm*32
    const int wn   = wid & 1;           // 0..1 : cols wn*64
    const int bid  = blockIdx.x;

    const int n_units = (NUNITS - 1 - bid) / GRID_MMA + 1;
    const int n_steps = n_units * 32;

    // per-lane ldmatrix swizzled address components
    const int rowA = wm * 32 + (lane & 15);
    const uint32_t offA = (uint32_t)(rowA * 128 + ((lane >> 4) * 8) * 2);
    const uint32_t xorA = (uint32_t)((rowA & 7) << 4);
    const int rowB = wn * 64 + (lane & 7) + ((lane & 16) ? 8 : 0);
    const uint32_t offB = (uint32_t)(rowB * 128 + (((lane >> 3) & 1) * 8) * 2);
    const uint32_t xorB = (uint32_t)((rowB & 7) << 4);

    float acc[2][8][4];
#pragma unroll
    for (int fm = 0; fm < 2; fm++)
#pragma unroll
        for (int nf = 0; nf < 8; nf++)
#pragma unroll
            for (int j = 0; j < 4; j++) acc[fm][nf][j] = 0.f;

    float best[4];
    int   bidx[4];
#pragma unroll
    for (int r = 0; r < 4; r++) { best[r] = 3.4e38f; bidx[r] = 0; }

    // -------- step t -> (unit, N-tile, slice) and stage load ----------------
    auto issue_load = [&](int t) {
        const int s    = t & 7;
        const int ntl  = (t >> 3) & 3;
        const int unit = bid + (t >> 5) * GRID_MMA;
        const int tt   = unit >> 3;          // 256-token pair index (0..127)
        const int nt128 = (unit & 7) * 4 + ntl;
        const uint32_t dst = sbase + (uint32_t)(t & 1) * STAGE_BYTES;
        const uint4* Ah0 = g_A + (((size_t)(2 * tt) * 16 + s) << 10);
        const uint4* Ah1 = Ah0 + (16 << 10);
        const uint4* Al0 = Ah0 + (8 << 10);
        const uint4* Al1 = Ah1 + (8 << 10);
        const uint4* Bh  = g_B + (((size_t)(nt128 >> 1) * 16 + s) << 11)
                               + (nt128 & 1) * 1024;
        const uint4* Bl  = Bh + (8 << 11);
#pragma unroll
        for (int i = 0; i < 2; i++) {
            int u = tid + 512 * i;
            cp16(dst + u * 16, Ah0 + u);                    // Ah rows 0-127
            cp16(dst + 16384 + u * 16, Ah1 + u);            // Ah rows 128-255
            cp16(dst + 32768 + u * 16, Al0 + u);            // Al rows 0-127
            cp16(dst + 49152 + u * 16, Al1 + u);            // Al rows 128-255
        }
#pragma unroll
        for (int i = 0; i < 2; i++) {
            int u = tid + 512 * i;
            cp16(dst + 65536 + u * 16, Bh + u);             // Bh 128 codes
            cp16(dst + 81920 + u * 16, Bl + u);             // Bl 128 codes
        }
        CP_COMMIT();
    };

    issue_load(0);

    for (int t = 0; t < n_steps; t++) {
        if (t < n_steps - 1) {
            issue_load(t + 1);
            asm volatile("cp.async.wait_group 1;" ::: "memory");
        } else {
            asm volatile("cp.async.wait_group 0;" ::: "memory");
        }
        __syncthreads();

        const uint32_t base = sbase + (uint32_t)(t & 1) * STAGE_BYTES;
#pragma unroll
        for (int k16 = 0; k16 < 4; k16++) {
            // A fragments for this k16: hi and lo, both M-halves.
            uint32_t aH[2][4], aL[2][4];
#pragma unroll
            for (int fm = 0; fm < 2; fm++) {
                ldm_x4(aH[fm], base + ((offA + fm * 2048 + k16 * 32) ^ xorA));
                ldm_x4(aL[fm], base + 32768u + ((offA + fm * 2048 + k16 * 32) ^ xorA));
            }
#pragma unroll
            for (int n4 = 0; n4 < 4; n4++) {
                uint32_t bh[4];
                ldm_x4(bh, base + 65536u + ((offB + n4 * 2048 + k16 * 32) ^ xorB));
#pragma unroll
                for (int fm = 0; fm < 2; fm++) {
                    mma16816(acc[fm][n4 * 2],     aH[fm], bh[0], bh[1]);
                    mma16816(acc[fm][n4 * 2 + 1], aH[fm], bh[2], bh[3]);
                    mma16816(acc[fm][n4 * 2],     aL[fm], bh[0], bh[1]);
                    mma16816(acc[fm][n4 * 2 + 1], aL[fm], bh[2], bh[3]);
                }
                uint32_t bl[4];
                ldm_x4(bl, base + 81920u + ((offB + n4 * 2048 + k16 * 32) ^ xorB));
#pragma unroll
                for (int fm = 0; fm < 2; fm++) {
                    mma16816(acc[fm][n4 * 2],     aH[fm], bl[0], bl[1]);
                    mma16816(acc[fm][n4 * 2 + 1], aH[fm], bl[2], bl[3]);
                }
            }
        }

        // ------- epilogue after last slice of each N-tile: score + argmin -------
        if ((t & 7) == 7) {
            const int unit  = bid + (t >> 5) * GRID_MMA;
            const int nt128 = (unit & 7) * 4 + ((t >> 3) & 3);
            const int colbase = nt128 * 128 + wn * 64 + (lane & 3) * 2;
#pragma unroll
            for (int nf = 0; nf < 8; nf++) {
                const int c0 = colbase + nf * 8;
                const float e0 = g_enorm[c0];
                const float e1 = g_enorm[c0 + 1];
#pragma unroll
                for (int fm = 0; fm < 2; fm++) {
                    float v0 = fmaf(-2.f, acc[fm][nf][0], e0);
                    float v1 = fmaf(-2.f, acc[fm][nf][1], e1);
                    float v2 = fmaf(-2.f, acc[fm][nf][2], e0);
                    float v3 = fmaf(-2.f, acc[fm][nf][3], e1);
                    if (v0 < best[fm * 2])     { best[fm * 2] = v0;     bidx[fm * 2] = c0; }
                    if (v1 < best[fm * 2])     { best[fm * 2] = v1;     bidx[fm * 2] = c0 + 1; }
                    if (v2 < best[fm * 2 + 1]) { best[fm * 2 + 1] = v2; bidx[fm * 2 + 1] = c0; }
                    if (v3 < best[fm * 2 + 1]) { best[fm * 2 + 1] = v3; bidx[fm * 2 + 1] = c0 + 1; }
                    acc[fm][nf][0] = 0.f; acc[fm][nf][1] = 0.f;
                    acc[fm][nf][2] = 0.f; acc[fm][nf][3] = 0.f;
                }
            }
        }

        // ------- unit boundary: flush per-token candidates to global best -------
        if ((t & 31) == 31) {
            const int unit = bid + (t >> 5) * GRID_MMA;
            const int tt   = unit >> 3;
#pragma unroll
            for (int r = 0; r < 4; r++) {
                float v = best[r];
                int   ix = bidx[r];
#pragma unroll
                for (int o = 1; o < 4; o <<= 1) {
                    float ov = __shfl_xor_sync(0xffffffffu, v, o);
                    int   oi = __shfl_xor_sync(0xffffffffu, ix, o);
                    if (ov < v || (ov == v && oi < ix)) { v = ov; ix = oi; }
                }
                if ((lane & 3) == 0) {
                    int fm = r >> 1, h = r & 1;
                    int R = wm * 32 + fm * 16 + h * 8 + (lane >> 2);
                    sval[R][wn] = v;
                    sidx[R][wn] = ix;
                }
                best[r] = 3.4e38f; bidx[r] = 0;
            }
            __syncthreads();
            if (tid < 256) {
                float v0 = sval[tid][0], v1 = sval[tid][1];
                int   i0 = sidx[tid][0], i1 = sidx[tid][1];
                bool take1 = (v1 < v0 || (v1 == v0 && i1 < i0));
                float v = take1 ? v1 : v0;
                int   ix = take1 ? i1 : i0;
                unsigned long long key =
                    ((unsigned long long)fkey(v) << 32) | (uint32_t)ix;
                atomicMin(&g_best[tt * 256 + tid], key);
            }
        }
        __syncthreads();   // buffer t+1's slot free before next issue_load
    }
}

// ---------------- kernel 4: gather -> NCHW output + loss partial ----------------
__global__ void gather_kernel(const float* __restrict__ in,
                              const float* __restrict__ E,
                              float* __restrict__ out) {
    int bd = blockIdx.x;
    int b = bd >> 9;
    int d = bd & 511;
    const unsigned long long* kp = g_best + b * HW;
    size_t base = ((size_t)b * DIM + d) * HW;
    float local = 0.f;
#pragma unroll
    for (int it = 0; it < 4; it++) {
        int hw = it * 256 + threadIdx.x;
        int k = (int)(kp[hw] & 0xFFFFFFFFULL);
        float e = E[(size_t)k * DIM + d];
        float z = in[base + hw];
        out[base + hw] = e;
        float df = z - e;
        local = fmaf(df, df, local);
    }
    __shared__ float red[256];
    red[threadIdx.x] = local;
    __syncthreads();
    for (int o = 128; o > 0; o >>= 1) {
        if (threadIdx.x < o) red[threadIdx.x] += red[threadIdx.x + o];
        __syncthreads();
    }
    if (threadIdx.x == 0) atomicAdd(&g_loss_acc, (double)red[0]);
}

// ---------------- kernel 5: final loss scalar -----------------------------------
__global__ void loss_kernel(float* __restrict__ out, int out_size) {
    if ((long long)out_size > TOTAL_OUT) {
        double mean = g_loss_acc / (double)TOTAL_OUT;
        out[TOTAL_OUT] = (float)(1.25 * mean);
    }
}

// ---------------- launch --------------------------------------------------------
extern "C" void kernel_launch(void* const* d_in, const int* in_sizes, int n_in,
                              void* d_out, int out_size) {
    const float* in = (const float*)d_in[0];   // [32,512,32,32] fp32
    const float* E  = (const float*)d_in[1];   // [4096,512] fp32
    float* out = (float*)d_out;

    cudaFuncSetAttribute(vq_mma_kernel,
                         cudaFuncAttributeMaxDynamicSharedMemorySize, SMEM_DYN);

    init_kernel<<<NTOK / 256, 256>>>();
    enorm_kernel<<<NCODE, 128>>>(E);
    convA_kernel<<<256 * 16, 256>>>(in);
    convB_kernel<<<16 * 16, 256>>>(E);
    vq_mma_kernel<<<GRID_MMA, 512, SMEM_DYN>>>();
    gather_kernel<<<BATCH * DIM, 256>>>(in, E, out);
    loss_kernel<<<1, 1>>>(out, out_size);
}